// round 6
// baseline (speedup 1.0000x reference)
#include <cuda_runtime.h>
#include <math.h>

#define NB_C   100000
#define SZ_D   64
#define SZ_B   1024
#define BM     128
#define BN     128
#define KC     32                 // k-chunk (2 chunks cover D=64)
#define PAD    36                 // tile row stride in floats: %32==4 -> conflict-free, %4==0 -> float4-aligned
#define CB     ((NB_C + BN - 1) / BN)   // 782 class blocks

typedef unsigned long long u64;

// ---- device scratch (no allocations allowed) ----
__device__ float g_Pn[(size_t)NB_C * SZ_D];   // normalized proxies, 25.6 MB
__device__ float g_psq[NB_C];                 // sum(Pn^2) per class
__device__ float g_partial[(size_t)SZ_B * CB];// per (row, class-block) exp-sums
__device__ float g_persample[SZ_B];
__device__ int   g_ys[SZ_B];                  // decoded labels (dtype-robust)

// packed fp32 FMA: d = a*b + d elementwise on (lo,hi) pairs
__device__ __forceinline__ void fma2(u64& d, u64 a, u64 b) {
    asm("fma.rn.f32x2 %0, %1, %2, %0;" : "+l"(d) : "l"(a), "l"(b));
}

// ============ Kernel 0: decode labels (int32 vs int64 robust) ============
__global__ void decode_ys_kernel(const int* __restrict__ ys32) {
    __shared__ int nonzero_odd;
    const int tid = threadIdx.x;           // 1024 threads
    if (tid == 0) nonzero_odd = 0;
    __syncthreads();
    if (tid < SZ_B / 2) {
        if (ys32[2 * tid + 1] != 0) atomicOr(&nonzero_odd, 1);
    }
    __syncthreads();
    if (nonzero_odd) {
        g_ys[tid] = ys32[tid];                          // genuine int32 labels
    } else {
        const long long* ys64 = (const long long*)ys32; // int64 labels
        g_ys[tid] = (int)ys64[tid];
    }
}

// ================= Kernel A: row-normalize proxies =================
__global__ void normalize_kernel(const float* __restrict__ proxies) {
    int row  = blockIdx.x * 8 + (threadIdx.x >> 5);
    int lane = threadIdx.x & 31;
    if (row >= NB_C) return;
    const float2 v = *(const float2*)(proxies + (size_t)row * SZ_D + lane * 2);
    float s = v.x * v.x + v.y * v.y;
    #pragma unroll
    for (int o = 16; o; o >>= 1) s += __shfl_xor_sync(0xffffffffu, s, o);
    float norm = sqrtf(s);
    float inv  = 1.0f / fmaxf(norm, 1e-12f);
    float2 w; w.x = v.x * inv; w.y = v.y * inv;
    *(float2*)(g_Pn + (size_t)row * SZ_D + lane * 2) = w;
    if (lane == 0) g_psq[row] = s * inv * inv;
}

// ===== Kernel B: f32x2-packed tiled GEMM + fused exp-sum epilogue =====
// Tiles are stored row-major (k contiguous) with PAD=36 so that both the
// float4 STS fills and the per-thread float4 LDS reads are bank-conflict-free.
// Per-thread: 8 rows (ty+16i) x 8 classes (tx+16j), accumulators packed over
// k-pairs; lo/hi halves summed in the epilogue.
__global__ void __launch_bounds__(256, 1)
gemm_lse_kernel(const float* __restrict__ xs) {
    __shared__ float As[BM * PAD];
    __shared__ float Bs[BN * PAD];
    __shared__ float Qs[BN];
    __shared__ int   Ys[BM];

    const int cb   = blockIdx.x;
    const int rb   = blockIdx.y;
    const int col0 = cb * BN;
    const int row0 = rb * BM;
    const int tid  = threadIdx.x;          // 256 threads
    const int tx   = tid & 15;             // class group (strided classes tx+16j)
    const int ty   = tid >> 4;             // row group   (strided rows  ty+16i)

    if (tid < BM) Ys[tid] = g_ys[row0 + tid];
    if (tid < BN) {
        int cls = col0 + tid;
        Qs[tid] = (cls < NB_C) ? g_psq[cls] : 0.0f;
    }

    u64 acc[8][8];
    #pragma unroll
    for (int i = 0; i < 8; i++)
        #pragma unroll
        for (int j = 0; j < 8; j++) acc[i][j] = 0ull;

    #pragma unroll
    for (int kc = 0; kc < SZ_D / KC; kc++) {
        // -- fill A tile: 128 rows x 32 k, row-major --
        #pragma unroll
        for (int i = 0; i < 4; i++) {
            int idx = tid + i * 256;           // 0..1023
            int r   = idx & 127;
            int kq  = idx >> 7;                // 0..7 (float4 group)
            float4 v = *(const float4*)(xs + (size_t)(row0 + r) * SZ_D + kc * KC + kq * 4);
            *(float4*)(As + r * PAD + kq * 4) = v;
        }
        // -- fill B tile: 128 classes x 32 k, row-major (guard tail) --
        #pragma unroll
        for (int i = 0; i < 4; i++) {
            int idx = tid + i * 256;
            int c   = idx & 127;
            int kq  = idx >> 7;
            int cls = col0 + c;
            float4 v = make_float4(0.f, 0.f, 0.f, 0.f);
            if (cls < NB_C)
                v = *(const float4*)(g_Pn + (size_t)cls * SZ_D + kc * KC + kq * 4);
            *(float4*)(Bs + c * PAD + kq * 4) = v;
        }
        __syncthreads();

        #pragma unroll
        for (int kk = 0; kk < KC; kk += 4) {
            ulonglong2 a2[8], b2[8];
            #pragma unroll
            for (int i = 0; i < 8; i++)
                a2[i] = *(const ulonglong2*)(As + (ty + 16 * i) * PAD + kk);
            #pragma unroll
            for (int j = 0; j < 8; j++)
                b2[j] = *(const ulonglong2*)(Bs + (tx + 16 * j) * PAD + kk);
            #pragma unroll
            for (int i = 0; i < 8; i++)
                #pragma unroll
                for (int j = 0; j < 8; j++) {
                    fma2(acc[i][j], a2[i].x, b2[j].x);
                    fma2(acc[i][j], a2[i].y, b2[j].y);
                }
        }
        __syncthreads();
    }

    // -- epilogue: dot = lo+hi ; g = 2*dot - psq ; sum exp(g) over negatives --
    int yv[8];
    float qs[8];
    #pragma unroll
    for (int i = 0; i < 8; i++) yv[i] = Ys[ty + 16 * i];
    #pragma unroll
    for (int j = 0; j < 8; j++) qs[j] = Qs[tx + 16 * j];

    #pragma unroll
    for (int i = 0; i < 8; i++) {
        float s = 0.0f;
        #pragma unroll
        for (int j = 0; j < 8; j++) {
            unsigned lo = (unsigned)(acc[i][j] & 0xffffffffull);
            unsigned hi = (unsigned)(acc[i][j] >> 32);
            float dot = __uint_as_float(lo) + __uint_as_float(hi);
            int cls = col0 + tx + 16 * j;
            float g = fmaf(2.0f, dot, -qs[j]);
            float e = __expf(g);
            if (cls >= NB_C || cls == yv[i]) e = 0.0f;
            s += e;
        }
        // reduce across the 16 tx lanes (xor 8..1 stays within the 16-lane half)
        #pragma unroll
        for (int o = 8; o >= 1; o >>= 1) s += __shfl_xor_sync(0xffffffffu, s, o);
        if (tx == 0) {
            int row = row0 + ty + 16 * i;
            g_partial[(size_t)row * CB + cb] = s;
        }
    }
}

// ===== Kernel C: per-row combine partials + positive distance =====
__global__ void combine_kernel(const float* __restrict__ xs) {
    const int row = blockIdx.x;
    const int tid = threadIdx.x;   // 128 threads
    const int y   = g_ys[row];

    float S = 0.0f;
    for (int p = tid; p < CB; p += 128) S += g_partial[(size_t)row * CB + p];

    float d = 0.0f;
    if (tid < SZ_D) d = xs[(size_t)row * SZ_D + tid] * g_Pn[(size_t)y * SZ_D + tid];

    #pragma unroll
    for (int o = 16; o; o >>= 1) {
        S += __shfl_xor_sync(0xffffffffu, S, o);
        d += __shfl_xor_sync(0xffffffffu, d, o);
    }
    __shared__ float sS[4], sD[4];
    int w = tid >> 5, lane = tid & 31;
    if (lane == 0) { sS[w] = S; sD[w] = d; }
    __syncthreads();
    if (tid == 0) {
        float St = sS[0] + sS[1] + sS[2] + sS[3];
        float Dt = sD[0] + sD[1] + sD[2] + sD[3];
        // per_sample = d_pos + log_n ; the ||x||^2 terms cancel exactly
        g_persample[row] = g_psq[y] - 2.0f * Dt + logf(St);
    }
}

// ===== Kernel D: mean over batch =====
__global__ void mean_kernel(float* __restrict__ out) {
    const int tid = threadIdx.x;   // 1024
    float v = g_persample[tid];
    #pragma unroll
    for (int o = 16; o; o >>= 1) v += __shfl_xor_sync(0xffffffffu, v, o);
    __shared__ float s[32];
    int w = tid >> 5, lane = tid & 31;
    if (lane == 0) s[w] = v;
    __syncthreads();
    if (tid < 32) {
        float t = s[tid];
        #pragma unroll
        for (int o = 16; o; o >>= 1) t += __shfl_xor_sync(0xffffffffu, t, o);
        if (tid == 0) out[0] = t * (1.0f / (float)SZ_B);
    }
}

extern "C" void kernel_launch(void* const* d_in, const int* in_sizes, int n_in,
                              void* d_out, int out_size) {
    const float* xs      = (const float*)d_in[0];
    const int*   ys_raw  = (const int*)d_in[1];
    const float* proxies = (const float*)d_in[2];
    float*       out     = (float*)d_out;

    decode_ys_kernel<<<1, SZ_B>>>(ys_raw);
    normalize_kernel<<<(NB_C + 7) / 8, 256>>>(proxies);
    gemm_lse_kernel<<<dim3(CB, SZ_B / BM), 256>>>(xs);
    combine_kernel<<<SZ_B, 128>>>(xs);
    mean_kernel<<<1, SZ_B>>>(out);
}

// round 7
// speedup vs baseline: 2.3809x; 2.3809x over previous
#include <cuda_runtime.h>
#include <math.h>

#define NB_C   100000
#define SZ_D   64
#define SZ_B   1024
#define BM     128
#define BN     128
#define KC     32                 // k-chunk (2 chunks cover D=64)
#define PAD    36                 // row stride in floats: (qr*36+qc)%32 = 4*qr+qc -> conflict-free
#define CB     ((NB_C + BN - 1) / BN)   // 782 class blocks

// ---- device scratch (no allocations allowed) ----
__device__ float g_Pn[(size_t)NB_C * SZ_D];   // normalized proxies (tf32-rounded), 25.6 MB
__device__ float g_psq[NB_C];                 // sum(Pn^2) per class (full fp32)
__device__ float g_partial[(size_t)SZ_B * CB];// per (row, class-block) exp-sums
__device__ float g_persample[SZ_B];
__device__ int   g_ys[SZ_B];                  // decoded labels (dtype-robust)

__device__ __forceinline__ unsigned cvt_tf32(float f) {
    unsigned u;
    asm("cvt.rna.tf32.f32 %0, %1;" : "=r"(u) : "f"(f));
    return u;
}

__device__ __forceinline__ void mma_tf32(float* d, const unsigned* a, const unsigned* b) {
    asm("mma.sync.aligned.m16n8k8.row.col.f32.tf32.tf32.f32 "
        "{%0,%1,%2,%3}, {%4,%5,%6,%7}, {%8,%9}, {%0,%1,%2,%3};"
        : "+f"(d[0]), "+f"(d[1]), "+f"(d[2]), "+f"(d[3])
        : "r"(a[0]), "r"(a[1]), "r"(a[2]), "r"(a[3]), "r"(b[0]), "r"(b[1]));
}

// ============ Kernel 0: decode labels (int32 vs int64 robust) ============
__global__ void decode_ys_kernel(const int* __restrict__ ys32) {
    __shared__ int nonzero_odd;
    const int tid = threadIdx.x;           // 1024 threads
    if (tid == 0) nonzero_odd = 0;
    __syncthreads();
    if (tid < SZ_B / 2) {
        if (ys32[2 * tid + 1] != 0) atomicOr(&nonzero_odd, 1);
    }
    __syncthreads();
    if (nonzero_odd) {
        g_ys[tid] = ys32[tid];                          // genuine int32 labels
    } else {
        const long long* ys64 = (const long long*)ys32; // int64 labels
        g_ys[tid] = (int)ys64[tid];
    }
}

// ================= Kernel A: row-normalize proxies =================
__global__ void normalize_kernel(const float* __restrict__ proxies) {
    int row  = blockIdx.x * 8 + (threadIdx.x >> 5);
    int lane = threadIdx.x & 31;
    if (row >= NB_C) return;
    const float2 v = *(const float2*)(proxies + (size_t)row * SZ_D + lane * 2);
    float s = v.x * v.x + v.y * v.y;
    #pragma unroll
    for (int o = 16; o; o >>= 1) s += __shfl_xor_sync(0xffffffffu, s, o);
    float norm = sqrtf(s);
    float inv  = 1.0f / fmaxf(norm, 1e-12f);
    float2 w; w.x = v.x * inv; w.y = v.y * inv;
    *(float2*)(g_Pn + (size_t)row * SZ_D + lane * 2) = w;
    if (lane == 0) g_psq[row] = s * inv * inv;
}

// ===== Kernel B: tf32 mma.sync GEMM + fused exp-sum epilogue =====
// 8 warps: warp_m in {0,1} (64 rows), warp_n in {0..3} (32 classes).
// Per warp: 4x4 m16n8k8 fragments, fp32 accumulate. Inputs RNA-rounded to tf32.
__global__ void __launch_bounds__(256, 2)
gemm_lse_kernel(const float* __restrict__ xs) {
    __shared__ float As[BM * PAD];
    __shared__ float Bs[BN * PAD];
    __shared__ float Qs[BN];
    __shared__ int   Ys[BM];
    __shared__ float RowSum[BM];

    const int cb   = blockIdx.x;
    const int rb   = blockIdx.y;
    const int col0 = cb * BN;
    const int row0 = rb * BM;
    const int tid  = threadIdx.x;          // 256 threads
    const int lane = tid & 31;
    const int warp = tid >> 5;
    const int wm   = warp >> 2;            // 0..1
    const int wn   = warp & 3;             // 0..3
    const int mb   = wm * 64;
    const int nb   = wn * 32;
    const int qr   = lane >> 2;            // 0..7
    const int qc   = lane & 3;             // 0..3

    if (tid < BM) { Ys[tid] = g_ys[row0 + tid]; RowSum[tid] = 0.0f; }
    if (tid < BN) {
        int cls = col0 + tid;
        Qs[tid] = (cls < NB_C) ? g_psq[cls] : 0.0f;
    }

    float acc[4][4][4];
    #pragma unroll
    for (int mf = 0; mf < 4; mf++)
        #pragma unroll
        for (int nf = 0; nf < 4; nf++)
            #pragma unroll
            for (int c = 0; c < 4; c++) acc[mf][nf][c] = 0.0f;

    #pragma unroll
    for (int kc = 0; kc < SZ_D / KC; kc++) {
        // -- fill A tile: 128 rows x 32 k, tf32-rounded --
        #pragma unroll
        for (int i = 0; i < 4; i++) {
            int idx = tid + i * 256;           // 0..1023
            int r   = idx & 127;
            int kq  = idx >> 7;                // 0..7 float4 group
            float4 v = *(const float4*)(xs + (size_t)(row0 + r) * SZ_D + kc * KC + kq * 4);
            float* p = As + r * PAD + kq * 4;
            p[0] = __uint_as_float(cvt_tf32(v.x));
            p[1] = __uint_as_float(cvt_tf32(v.y));
            p[2] = __uint_as_float(cvt_tf32(v.z));
            p[3] = __uint_as_float(cvt_tf32(v.w));
        }
        // -- fill B tile: 128 classes x 32 k, tf32-rounded (tail guard) --
        #pragma unroll
        for (int i = 0; i < 4; i++) {
            int idx = tid + i * 256;
            int c   = idx & 127;
            int kq  = idx >> 7;
            int cls = col0 + c;
            float4 v = make_float4(0.f, 0.f, 0.f, 0.f);
            if (cls < NB_C)
                v = *(const float4*)(g_Pn + (size_t)cls * SZ_D + kc * KC + kq * 4);
            float* p = Bs + c * PAD + kq * 4;
            p[0] = __uint_as_float(cvt_tf32(v.x));
            p[1] = __uint_as_float(cvt_tf32(v.y));
            p[2] = __uint_as_float(cvt_tf32(v.z));
            p[3] = __uint_as_float(cvt_tf32(v.w));
        }
        __syncthreads();

        #pragma unroll
        for (int s = 0; s < KC / 8; s++) {
            const int kb = s * 8;
            unsigned a[4][4], b[4][2];
            #pragma unroll
            for (int mf = 0; mf < 4; mf++) {
                int r = mb + mf * 16 + qr;
                a[mf][0] = __float_as_uint(As[r * PAD + kb + qc]);
                a[mf][1] = __float_as_uint(As[(r + 8) * PAD + kb + qc]);
                a[mf][2] = __float_as_uint(As[r * PAD + kb + qc + 4]);
                a[mf][3] = __float_as_uint(As[(r + 8) * PAD + kb + qc + 4]);
            }
            #pragma unroll
            for (int nf = 0; nf < 4; nf++) {
                int n = nb + nf * 8 + qr;
                b[nf][0] = __float_as_uint(Bs[n * PAD + kb + qc]);
                b[nf][1] = __float_as_uint(Bs[n * PAD + kb + qc + 4]);
            }
            #pragma unroll
            for (int mf = 0; mf < 4; mf++)
                #pragma unroll
                for (int nf = 0; nf < 4; nf++)
                    mma_tf32(acc[mf][nf], a[mf], b[nf]);
        }
        __syncthreads();
    }

    // -- epilogue: g = 2*dot - psq ; exp-sum over valid negatives --
    // fragment C layout: c0 -> (row qr, col 2*qc), c1 -> (qr, 2*qc+1),
    //                    c2 -> (qr+8, 2*qc), c3 -> (qr+8, 2*qc+1)
    #pragma unroll
    for (int mf = 0; mf < 4; mf++) {
        int r0 = mb + mf * 16 + qr;
        int r1 = r0 + 8;
        int y0 = Ys[r0], y1 = Ys[r1];
        float s0 = 0.0f, s1 = 0.0f;
        #pragma unroll
        for (int nf = 0; nf < 4; nf++) {
            #pragma unroll
            for (int c = 0; c < 4; c++) {
                int col = nb + nf * 8 + qc * 2 + (c & 1);
                int cls = col0 + col;
                int row_y = (c < 2) ? y0 : y1;
                float g = fmaf(2.0f, acc[mf][nf][c], -Qs[col]);
                float e = __expf(g);
                if (cls >= NB_C || cls == row_y) e = 0.0f;
                if (c < 2) s0 += e; else s1 += e;
            }
        }
        // reduce across the 4 lanes of the quad (same qr, different qc)
        #pragma unroll
        for (int o = 1; o <= 2; o <<= 1) {
            s0 += __shfl_xor_sync(0xffffffffu, s0, o);
            s1 += __shfl_xor_sync(0xffffffffu, s1, o);
        }
        if (qc == 0) {
            atomicAdd(&RowSum[r0], s0);
            atomicAdd(&RowSum[r1], s1);
        }
    }
    __syncthreads();
    if (tid < BM)
        g_partial[(size_t)(row0 + tid) * CB + cb] = RowSum[tid];
}

// ===== Kernel C: per-row combine partials + positive distance =====
__global__ void combine_kernel(const float* __restrict__ xs) {
    const int row = blockIdx.x;
    const int tid = threadIdx.x;   // 128 threads
    const int y   = g_ys[row];

    float S = 0.0f;
    for (int p = tid; p < CB; p += 128) S += g_partial[(size_t)row * CB + p];

    float d = 0.0f;
    if (tid < SZ_D) d = xs[(size_t)row * SZ_D + tid] * g_Pn[(size_t)y * SZ_D + tid];

    #pragma unroll
    for (int o = 16; o; o >>= 1) {
        S += __shfl_xor_sync(0xffffffffu, S, o);
        d += __shfl_xor_sync(0xffffffffu, d, o);
    }
    __shared__ float sS[4], sD[4];
    int w = tid >> 5, lane = tid & 31;
    if (lane == 0) { sS[w] = S; sD[w] = d; }
    __syncthreads();
    if (tid == 0) {
        float St = sS[0] + sS[1] + sS[2] + sS[3];
        float Dt = sD[0] + sD[1] + sD[2] + sD[3];
        // per_sample = d_pos + log_n ; the ||x||^2 terms cancel exactly
        g_persample[row] = g_psq[y] - 2.0f * Dt + logf(St);
    }
}

// ===== Kernel D: mean over batch =====
__global__ void mean_kernel(float* __restrict__ out) {
    const int tid = threadIdx.x;   // 1024
    float v = g_persample[tid];
    #pragma unroll
    for (int o = 16; o; o >>= 1) v += __shfl_xor_sync(0xffffffffu, v, o);
    __shared__ float s[32];
    int w = tid >> 5, lane = tid & 31;
    if (lane == 0) s[w] = v;
    __syncthreads();
    if (tid < 32) {
        float t = s[tid];
        #pragma unroll
        for (int o = 16; o; o >>= 1) t += __shfl_xor_sync(0xffffffffu, t, o);
        if (tid == 0) out[0] = t * (1.0f / (float)SZ_B);
    }
}

extern "C" void kernel_launch(void* const* d_in, const int* in_sizes, int n_in,
                              void* d_out, int out_size) {
    const float* xs      = (const float*)d_in[0];
    const int*   ys_raw  = (const int*)d_in[1];
    const float* proxies = (const float*)d_in[2];
    float*       out     = (float*)d_out;

    decode_ys_kernel<<<1, SZ_B>>>(ys_raw);
    normalize_kernel<<<(NB_C + 7) / 8, 256>>>(proxies);
    gemm_lse_kernel<<<dim3(CB, SZ_B / BM), 256>>>(xs);
    combine_kernel<<<SZ_B, 128>>>(xs);
    mean_kernel<<<1, SZ_B>>>(out);
}

// round 8
// speedup vs baseline: 4.5568x; 1.9139x over previous
#include <cuda_runtime.h>
#include <cuda_bf16.h>
#include <math.h>

#define NB_C   100000
#define SZ_D   64
#define SZ_B   1024
#define BM     128
#define BN     128
#define LDT    72                 // smem tile row stride in bf16 (144 B): 8 rows cover 8 distinct 16B banks
#define CB     ((NB_C + BN - 1) / BN)   // 782 class blocks

// ---- device scratch (no allocations allowed) ----
__device__ float          g_Pn [(size_t)NB_C * SZ_D];  // normalized proxies fp32 (combine only)
__device__ __nv_bfloat16  g_Pb [(size_t)NB_C * SZ_D];  // normalized proxies bf16 (GEMM B)
__device__ __nv_bfloat16  g_Xb [(size_t)SZ_B * SZ_D];  // xs bf16 (GEMM A)
__device__ float          g_psq[NB_C];                 // sum(Pn^2), exact fp32
__device__ float          g_partial[(size_t)SZ_B * CB];
__device__ float          g_persample[SZ_B];
__device__ int            g_ys[SZ_B];

__device__ __forceinline__ void ldsm_x4(unsigned& r0, unsigned& r1, unsigned& r2, unsigned& r3,
                                        unsigned saddr) {
    asm volatile("ldmatrix.sync.aligned.m8n8.x4.shared.b16 {%0,%1,%2,%3}, [%4];"
                 : "=r"(r0), "=r"(r1), "=r"(r2), "=r"(r3) : "r"(saddr));
}

__device__ __forceinline__ void mma_bf16(float* d, const unsigned* a, const unsigned* b) {
    asm("mma.sync.aligned.m16n8k16.row.col.f32.bf16.bf16.f32 "
        "{%0,%1,%2,%3}, {%4,%5,%6,%7}, {%8,%9}, {%0,%1,%2,%3};"
        : "+f"(d[0]), "+f"(d[1]), "+f"(d[2]), "+f"(d[3])
        : "r"(a[0]), "r"(a[1]), "r"(a[2]), "r"(a[3]), "r"(b[0]), "r"(b[1]));
}

// ============ Kernel 0: decode labels (int32 vs int64 robust) ============
__global__ void decode_ys_kernel(const int* __restrict__ ys32) {
    __shared__ int nonzero_odd;
    const int tid = threadIdx.x;           // 1024 threads
    if (tid == 0) nonzero_odd = 0;
    __syncthreads();
    if (tid < SZ_B / 2) {
        if (ys32[2 * tid + 1] != 0) atomicOr(&nonzero_odd, 1);
    }
    __syncthreads();
    if (nonzero_odd) g_ys[tid] = ys32[tid];
    else             g_ys[tid] = (int)((const long long*)ys32)[tid];
}

// ============ Kernel 0b: xs -> bf16 ============
__global__ void cvt_xs_kernel(const float* __restrict__ xs) {
    int i = blockIdx.x * 256 + threadIdx.x;          // 16384 float4 groups
    float4 v = *(const float4*)(xs + (size_t)i * 4);
    __nv_bfloat162 lo = __floats2bfloat162_rn(v.x, v.y);
    __nv_bfloat162 hi = __floats2bfloat162_rn(v.z, v.w);
    *(unsigned*)(g_Xb + (size_t)i * 4)     = *(unsigned*)&lo;
    *(unsigned*)(g_Xb + (size_t)i * 4 + 2) = *(unsigned*)&hi;
}

// ================= Kernel A: row-normalize proxies (fp32 + bf16 out) =================
__global__ void normalize_kernel(const float* __restrict__ proxies) {
    int row  = blockIdx.x * 8 + (threadIdx.x >> 5);
    int lane = threadIdx.x & 31;
    if (row >= NB_C) return;
    const float2 v = *(const float2*)(proxies + (size_t)row * SZ_D + lane * 2);
    float s = v.x * v.x + v.y * v.y;
    #pragma unroll
    for (int o = 16; o; o >>= 1) s += __shfl_xor_sync(0xffffffffu, s, o);
    float norm = sqrtf(s);
    float inv  = 1.0f / fmaxf(norm, 1e-12f);
    float2 w; w.x = v.x * inv; w.y = v.y * inv;
    *(float2*)(g_Pn + (size_t)row * SZ_D + lane * 2) = w;
    __nv_bfloat162 wb = __floats2bfloat162_rn(w.x, w.y);
    *(unsigned*)(g_Pb + (size_t)row * SZ_D + lane * 2) = *(unsigned*)&wb;
    if (lane == 0) g_psq[row] = s * inv * inv;
}

// ===== Kernel B: bf16 mma.sync GEMM (ldmatrix) + fused exp-sum epilogue =====
// 8 warps: wm in {0,1} x wn in {0..3}; warp tile 64x32; K=64 in one smem pass.
__global__ void __launch_bounds__(256, 2)
gemm_lse_kernel(void) {
    __shared__ __nv_bfloat16 As[BM * LDT];
    __shared__ __nv_bfloat16 Bs[BN * LDT];
    __shared__ float Qs[BN];
    __shared__ int   Ys[BM];
    __shared__ float RowSum[BM];

    const int cb   = blockIdx.x;
    const int rb   = blockIdx.y;
    const int col0 = cb * BN;
    const int row0 = rb * BM;
    const int tid  = threadIdx.x;          // 256
    const int lane = tid & 31;
    const int warp = tid >> 5;
    const int wm   = warp >> 2;            // 0..1
    const int wn   = warp & 3;             // 0..3
    const int mb   = wm * 64;
    const int nb   = wn * 32;
    const int qr   = lane >> 2;            // 0..7
    const int qc   = lane & 3;             // 0..3

    if (tid < BM) { Ys[tid] = g_ys[row0 + tid]; RowSum[tid] = 0.0f; }
    if (tid < BN) {
        int cls = col0 + tid;
        Qs[tid] = (cls < NB_C) ? g_psq[cls] : 0.0f;
    }

    // -- fill A tile: 128 rows x 64 bf16 (8 x 16B chunks per row) --
    #pragma unroll
    for (int i = 0; i < 4; i++) {
        int idx = tid + i * 256;           // 0..1023
        int r   = idx >> 3;
        int c   = idx & 7;
        uint4 v = ((const uint4*)(g_Xb + (size_t)(row0 + r) * SZ_D))[c];
        *(uint4*)((char*)As + r * (LDT * 2) + c * 16) = v;
    }
    // -- fill B tile: 128 classes x 64 bf16 (tail guard) --
    #pragma unroll
    for (int i = 0; i < 4; i++) {
        int idx = tid + i * 256;
        int r   = idx >> 3;
        int c   = idx & 7;
        int cls = col0 + r;
        uint4 v = make_uint4(0u, 0u, 0u, 0u);
        if (cls < NB_C)
            v = ((const uint4*)(g_Pb + (size_t)cls * SZ_D))[c];
        *(uint4*)((char*)Bs + r * (LDT * 2) + c * 16) = v;
    }
    __syncthreads();

    float acc[4][4][4];
    #pragma unroll
    for (int mf = 0; mf < 4; mf++)
        #pragma unroll
        for (int nf = 0; nf < 4; nf++)
            #pragma unroll
            for (int c = 0; c < 4; c++) acc[mf][nf][c] = 0.0f;

    // ldmatrix lane->address bases (byte offsets into shared space)
    const unsigned As_base = (unsigned)__cvta_generic_to_shared(As);
    const unsigned Bs_base = (unsigned)__cvta_generic_to_shared(Bs);
    // A: lanes 0-7 rows m0-7 chunk0 | 8-15 rows m8-15 chunk0 | 16-23 m0-7 chunk1 | 24-31 m8-15 chunk1
    const unsigned a_addr0 = As_base + (mb + (lane & 15)) * (LDT * 2) + (lane >> 4) * 16;
    // B: lanes 0-7 rows n0-7 chunk0 | 8-15 n0-7 chunk1 | 16-23 n8-15 chunk0 | 24-31 n8-15 chunk1
    const unsigned b_addr0 = Bs_base + (nb + ((lane >> 4) << 3) + (lane & 7)) * (LDT * 2)
                                     + (((lane >> 3) & 1)) * 16;

    #pragma unroll
    for (int s = 0; s < SZ_D / 16; s++) {          // 4 k16-steps
        unsigned a[4][4], b[4][2];
        #pragma unroll
        for (int mf = 0; mf < 4; mf++)
            ldsm_x4(a[mf][0], a[mf][1], a[mf][2], a[mf][3],
                    a_addr0 + mf * 16 * (LDT * 2) + s * 32);
        #pragma unroll
        for (int np = 0; np < 2; np++)             // each x4 covers 2 n-frags
            ldsm_x4(b[2 * np][0], b[2 * np][1], b[2 * np + 1][0], b[2 * np + 1][1],
                    b_addr0 + np * 16 * (LDT * 2) + s * 32);
        #pragma unroll
        for (int mf = 0; mf < 4; mf++)
            #pragma unroll
            for (int nf = 0; nf < 4; nf++)
                mma_bf16(acc[mf][nf], a[mf], b[nf]);
    }

    // -- epilogue: g = 2*dot - psq ; exp-sum over valid negatives --
    // C frag: c0->(qr, 2qc), c1->(qr, 2qc+1), c2->(qr+8, 2qc), c3->(qr+8, 2qc+1)
    #pragma unroll
    for (int mf = 0; mf < 4; mf++) {
        int r0 = mb + mf * 16 + qr;
        int r1 = r0 + 8;
        int y0 = Ys[r0], y1 = Ys[r1];
        float s0 = 0.0f, s1 = 0.0f;
        #pragma unroll
        for (int nf = 0; nf < 4; nf++) {
            #pragma unroll
            for (int c = 0; c < 4; c++) {
                int col = nb + nf * 8 + qc * 2 + (c & 1);
                int cls = col0 + col;
                int row_y = (c < 2) ? y0 : y1;
                float g = fmaf(2.0f, acc[mf][nf][c], -Qs[col]);
                float e = __expf(g);
                if (cls >= NB_C || cls == row_y) e = 0.0f;
                if (c < 2) s0 += e; else s1 += e;
            }
        }
        #pragma unroll
        for (int o = 1; o <= 2; o <<= 1) {
            s0 += __shfl_xor_sync(0xffffffffu, s0, o);
            s1 += __shfl_xor_sync(0xffffffffu, s1, o);
        }
        if (qc == 0) {
            atomicAdd(&RowSum[r0], s0);
            atomicAdd(&RowSum[r1], s1);
        }
    }
    __syncthreads();
    if (tid < BM)
        g_partial[(size_t)(row0 + tid) * CB + cb] = RowSum[tid];
}

// ===== Kernel C: per-row combine partials + positive distance (exact fp32) =====
__global__ void combine_kernel(const float* __restrict__ xs) {
    const int row = blockIdx.x;
    const int tid = threadIdx.x;   // 256 threads
    const int y   = g_ys[row];

    float S = 0.0f;
    for (int p = tid; p < CB; p += 256) S += g_partial[(size_t)row * CB + p];

    float d = 0.0f;
    if (tid < SZ_D) d = xs[(size_t)row * SZ_D + tid] * g_Pn[(size_t)y * SZ_D + tid];

    #pragma unroll
    for (int o = 16; o; o >>= 1) {
        S += __shfl_xor_sync(0xffffffffu, S, o);
        d += __shfl_xor_sync(0xffffffffu, d, o);
    }
    __shared__ float sS[8], sD[8];
    int w = tid >> 5, lane = tid & 31;
    if (lane == 0) { sS[w] = S; sD[w] = d; }
    __syncthreads();
    if (tid == 0) {
        float St = 0.0f, Dt = 0.0f;
        #pragma unroll
        for (int k = 0; k < 8; k++) { St += sS[k]; Dt += sD[k]; }
        // per_sample = d_pos + log_n ; the ||x||^2 terms cancel exactly
        g_persample[row] = g_psq[y] - 2.0f * Dt + logf(St);
    }
}

// ===== Kernel D: mean over batch =====
__global__ void mean_kernel(float* __restrict__ out) {
    const int tid = threadIdx.x;   // 1024
    float v = g_persample[tid];
    #pragma unroll
    for (int o = 16; o; o >>= 1) v += __shfl_xor_sync(0xffffffffu, v, o);
    __shared__ float s[32];
    int w = tid >> 5, lane = tid & 31;
    if (lane == 0) s[w] = v;
    __syncthreads();
    if (tid < 32) {
        float t = s[tid];
        #pragma unroll
        for (int o = 16; o; o >>= 1) t += __shfl_xor_sync(0xffffffffu, t, o);
        if (tid == 0) out[0] = t * (1.0f / (float)SZ_B);
    }
}

extern "C" void kernel_launch(void* const* d_in, const int* in_sizes, int n_in,
                              void* d_out, int out_size) {
    const float* xs      = (const float*)d_in[0];
    const int*   ys_raw  = (const int*)d_in[1];
    const float* proxies = (const float*)d_in[2];
    float*       out     = (float*)d_out;

    decode_ys_kernel<<<1, SZ_B>>>(ys_raw);
    cvt_xs_kernel<<<(SZ_B * SZ_D / 4) / 256, 256>>>(xs);
    normalize_kernel<<<(NB_C + 7) / 8, 256>>>(proxies);
    gemm_lse_kernel<<<dim3(CB, SZ_B / BM), 256>>>();
    combine_kernel<<<SZ_B, 256>>>(xs);
    mean_kernel<<<1, SZ_B>>>(out);
}

// round 9
// speedup vs baseline: 5.4733x; 1.2011x over previous
#include <cuda_runtime.h>
#include <cuda_bf16.h>
#include <math.h>

#define NB_C   100000
#define SZ_D   64
#define SZ_B   1024
#define BM     128
#define BN     128
#define LDT    72                 // smem tile row stride in bf16 (144 B)
#define CB     ((NB_C + BN - 1) / BN)   // 782 class blocks
#define N_PAD  (CB * BN - NB_C)         // 96 pad classes, each contributes exactly 1.0
#define LOG2E  1.4426950408889634f

// ---- device scratch (no allocations allowed) ----
__device__ float          g_Pn [(size_t)NB_C * SZ_D];  // normalized proxies fp32 (combine only)
__device__ __nv_bfloat16  g_Pb [(size_t)NB_C * SZ_D];  // normalized proxies bf16 (GEMM B)
__device__ __nv_bfloat16  g_Xb [(size_t)SZ_B * SZ_D];  // xs bf16 (GEMM A)
__device__ float          g_psq[NB_C];                 // sum(Pn^2), exact fp32
__device__ float          g_partial[(size_t)SZ_B * CB];
__device__ float          g_persample[SZ_B];
__device__ int            g_ys[SZ_B];

__device__ __forceinline__ void ldsm_x4(unsigned& r0, unsigned& r1, unsigned& r2, unsigned& r3,
                                        unsigned saddr) {
    asm volatile("ldmatrix.sync.aligned.m8n8.x4.shared.b16 {%0,%1,%2,%3}, [%4];"
                 : "=r"(r0), "=r"(r1), "=r"(r2), "=r"(r3) : "r"(saddr));
}

__device__ __forceinline__ void mma_bf16(float* d, const unsigned* a, const unsigned* b) {
    asm("mma.sync.aligned.m16n8k16.row.col.f32.bf16.bf16.f32 "
        "{%0,%1,%2,%3}, {%4,%5,%6,%7}, {%8,%9}, {%0,%1,%2,%3};"
        : "+f"(d[0]), "+f"(d[1]), "+f"(d[2]), "+f"(d[3])
        : "r"(a[0]), "r"(a[1]), "r"(a[2]), "r"(a[3]), "r"(b[0]), "r"(b[1]));
}

// ============ Kernel 0: decode labels (int32 vs int64 robust) ============
__global__ void decode_ys_kernel(const int* __restrict__ ys32) {
    __shared__ int nonzero_odd;
    const int tid = threadIdx.x;           // 1024 threads
    if (tid == 0) nonzero_odd = 0;
    __syncthreads();
    if (tid < SZ_B / 2) {
        if (ys32[2 * tid + 1] != 0) atomicOr(&nonzero_odd, 1);
    }
    __syncthreads();
    if (nonzero_odd) g_ys[tid] = ys32[tid];
    else             g_ys[tid] = (int)((const long long*)ys32)[tid];
}

// ============ Kernel 0b: xs -> bf16 ============
__global__ void cvt_xs_kernel(const float* __restrict__ xs) {
    int i = blockIdx.x * 256 + threadIdx.x;          // 16384 float4 groups
    float4 v = *(const float4*)(xs + (size_t)i * 4);
    __nv_bfloat162 lo = __floats2bfloat162_rn(v.x, v.y);
    __nv_bfloat162 hi = __floats2bfloat162_rn(v.z, v.w);
    *(unsigned*)(g_Xb + (size_t)i * 4)     = *(unsigned*)&lo;
    *(unsigned*)(g_Xb + (size_t)i * 4 + 2) = *(unsigned*)&hi;
}

// ================= Kernel A: row-normalize proxies (fp32 + bf16 out) =================
__global__ void normalize_kernel(const float* __restrict__ proxies) {
    int row  = blockIdx.x * 8 + (threadIdx.x >> 5);
    int lane = threadIdx.x & 31;
    if (row >= NB_C) return;
    const float2 v = *(const float2*)(proxies + (size_t)row * SZ_D + lane * 2);
    float s = v.x * v.x + v.y * v.y;
    #pragma unroll
    for (int o = 16; o; o >>= 1) s += __shfl_xor_sync(0xffffffffu, s, o);
    float norm = sqrtf(s);
    float inv  = 1.0f / fmaxf(norm, 1e-12f);
    float2 w; w.x = v.x * inv; w.y = v.y * inv;
    *(float2*)(g_Pn + (size_t)row * SZ_D + lane * 2) = w;
    __nv_bfloat162 wb = __floats2bfloat162_rn(w.x, w.y);
    *(unsigned*)(g_Pb + (size_t)row * SZ_D + lane * 2) = *(unsigned*)&wb;
    if (lane == 0) g_psq[row] = s * inv * inv;
}

// ===== Kernel B: bf16 mma GEMM + UNMASKED exp-sum epilogue =====
// Sums exp over ALL 128 columns (pads contribute exactly 1.0 each; the
// positive-class term is subtracted exactly in combine_kernel).
__global__ void __launch_bounds__(256, 2)
gemm_lse_kernel(void) {
    __shared__ __nv_bfloat16 As[BM * LDT];
    __shared__ __nv_bfloat16 Bs[BN * LDT];
    __shared__ float Qs2[BN];              // psq * log2e (0 for pads)
    __shared__ float RowSum[BM];

    const int cb   = blockIdx.x;
    const int rb   = blockIdx.y;
    const int col0 = cb * BN;
    const int row0 = rb * BM;
    const int tid  = threadIdx.x;          // 256
    const int lane = tid & 31;
    const int warp = tid >> 5;
    const int wm   = warp >> 2;            // 0..1
    const int wn   = warp & 3;             // 0..3
    const int mb   = wm * 64;
    const int nb   = wn * 32;
    const int qr   = lane >> 2;            // 0..7
    const int qc   = lane & 3;             // 0..3

    if (tid < BM) RowSum[tid] = 0.0f;
    if (tid < BN) {
        int cls = col0 + tid;
        Qs2[tid] = (cls < NB_C) ? g_psq[cls] * LOG2E : 0.0f;
    }

    // -- fill A tile: 128 rows x 64 bf16 (8 x 16B chunks per row) --
    #pragma unroll
    for (int i = 0; i < 4; i++) {
        int idx = tid + i * 256;           // 0..1023
        int r   = idx >> 3;
        int c   = idx & 7;
        uint4 v = ((const uint4*)(g_Xb + (size_t)(row0 + r) * SZ_D))[c];
        *(uint4*)((char*)As + r * (LDT * 2) + c * 16) = v;
    }
    // -- fill B tile: 128 classes x 64 bf16 (pads -> exact zeros) --
    #pragma unroll
    for (int i = 0; i < 4; i++) {
        int idx = tid + i * 256;
        int r   = idx >> 3;
        int c   = idx & 7;
        int cls = col0 + r;
        uint4 v = make_uint4(0u, 0u, 0u, 0u);
        if (cls < NB_C)
            v = ((const uint4*)(g_Pb + (size_t)cls * SZ_D))[c];
        *(uint4*)((char*)Bs + r * (LDT * 2) + c * 16) = v;
    }
    __syncthreads();

    float acc[4][4][4];
    #pragma unroll
    for (int mf = 0; mf < 4; mf++)
        #pragma unroll
        for (int nf = 0; nf < 4; nf++)
            #pragma unroll
            for (int c = 0; c < 4; c++) acc[mf][nf][c] = 0.0f;

    const unsigned As_base = (unsigned)__cvta_generic_to_shared(As);
    const unsigned Bs_base = (unsigned)__cvta_generic_to_shared(Bs);
    const unsigned a_addr0 = As_base + (mb + (lane & 15)) * (LDT * 2) + (lane >> 4) * 16;
    const unsigned b_addr0 = Bs_base + (nb + ((lane >> 4) << 3) + (lane & 7)) * (LDT * 2)
                                     + (((lane >> 3) & 1)) * 16;

    #pragma unroll
    for (int s = 0; s < SZ_D / 16; s++) {          // 4 k16-steps
        unsigned a[4][4], b[4][2];
        #pragma unroll
        for (int mf = 0; mf < 4; mf++)
            ldsm_x4(a[mf][0], a[mf][1], a[mf][2], a[mf][3],
                    a_addr0 + mf * 16 * (LDT * 2) + s * 32);
        #pragma unroll
        for (int np = 0; np < 2; np++)
            ldsm_x4(b[2 * np][0], b[2 * np][1], b[2 * np + 1][0], b[2 * np + 1][1],
                    b_addr0 + np * 16 * (LDT * 2) + s * 32);
        #pragma unroll
        for (int mf = 0; mf < 4; mf++)
            #pragma unroll
            for (int nf = 0; nf < 4; nf++)
                mma_bf16(acc[mf][nf], a[mf], b[nf]);
    }

    // -- epilogue: e = exp2(2*log2e*acc - psq*log2e), no masks --
    // preload this lane's 8 column constants (reused across all 4 mf)
    float q2[4][2];
    #pragma unroll
    for (int nf = 0; nf < 4; nf++) {
        int colp = nb + nf * 8 + qc * 2;
        q2[nf][0] = Qs2[colp];
        q2[nf][1] = Qs2[colp + 1];
    }
    const float TWO_L2E = 2.0f * LOG2E;

    #pragma unroll
    for (int mf = 0; mf < 4; mf++) {
        int r0 = mb + mf * 16 + qr;
        float s0 = 0.0f, s1 = 0.0f;
        #pragma unroll
        for (int nf = 0; nf < 4; nf++) {
            s0 += exp2f(fmaf(TWO_L2E, acc[mf][nf][0], -q2[nf][0]));
            s0 += exp2f(fmaf(TWO_L2E, acc[mf][nf][1], -q2[nf][1]));
            s1 += exp2f(fmaf(TWO_L2E, acc[mf][nf][2], -q2[nf][0]));
            s1 += exp2f(fmaf(TWO_L2E, acc[mf][nf][3], -q2[nf][1]));
        }
        #pragma unroll
        for (int o = 1; o <= 2; o <<= 1) {
            s0 += __shfl_xor_sync(0xffffffffu, s0, o);
            s1 += __shfl_xor_sync(0xffffffffu, s1, o);
        }
        if (qc == 0) {
            atomicAdd(&RowSum[r0], s0);
            atomicAdd(&RowSum[r0 + 8], s1);
        }
    }
    __syncthreads();
    if (tid < BM)
        g_partial[(size_t)(row0 + tid) * CB + cb] = RowSum[tid];
}

// ===== Kernel C: combine partials, subtract pads + positive term (exact fp32) =====
__global__ void combine_kernel(const float* __restrict__ xs) {
    const int row = blockIdx.x;
    const int tid = threadIdx.x;   // 256 threads
    const int y   = g_ys[row];

    float S = 0.0f;
    for (int p = tid; p < CB; p += 256) S += g_partial[(size_t)row * CB + p];

    float d = 0.0f;
    if (tid < SZ_D) d = xs[(size_t)row * SZ_D + tid] * g_Pn[(size_t)y * SZ_D + tid];

    #pragma unroll
    for (int o = 16; o; o >>= 1) {
        S += __shfl_xor_sync(0xffffffffu, S, o);
        d += __shfl_xor_sync(0xffffffffu, d, o);
    }
    __shared__ float sS[8], sD[8];
    int w = tid >> 5, lane = tid & 31;
    if (lane == 0) { sS[w] = S; sD[w] = d; }
    __syncthreads();
    if (tid == 0) {
        float St = 0.0f, Dt = 0.0f;
        #pragma unroll
        for (int k = 0; k < 8; k++) { St += sS[k]; Dt += sD[k]; }
        float psq_y = g_psq[y];
        // remove the 96 pad ones (exact) and the positive-class exp term
        float Sneg = St - (float)N_PAD - __expf(fmaf(2.0f, Dt, -psq_y));
        // per_sample = d_pos + log_n ; the ||x||^2 terms cancel exactly
        g_persample[row] = psq_y - 2.0f * Dt + logf(Sneg);
    }
}

// ===== Kernel D: mean over batch =====
__global__ void mean_kernel(float* __restrict__ out) {
    const int tid = threadIdx.x;   // 1024
    float v = g_persample[tid];
    #pragma unroll
    for (int o = 16; o; o >>= 1) v += __shfl_xor_sync(0xffffffffu, v, o);
    __shared__ float s[32];
    int w = tid >> 5, lane = tid & 31;
    if (lane == 0) s[w] = v;
    __syncthreads();
    if (tid < 32) {
        float t = s[tid];
        #pragma unroll
        for (int o = 16; o; o >>= 1) t += __shfl_xor_sync(0xffffffffu, t, o);
        if (tid == 0) out[0] = t * (1.0f / (float)SZ_B);
    }
}

extern "C" void kernel_launch(void* const* d_in, const int* in_sizes, int n_in,
                              void* d_out, int out_size) {
    const float* xs      = (const float*)d_in[0];
    const int*   ys_raw  = (const int*)d_in[1];
    const float* proxies = (const float*)d_in[2];
    float*       out     = (float*)d_out;

    decode_ys_kernel<<<1, SZ_B>>>(ys_raw);
    cvt_xs_kernel<<<(SZ_B * SZ_D / 4) / 256, 256>>>(xs);
    normalize_kernel<<<(NB_C + 7) / 8, 256>>>(proxies);
    gemm_lse_kernel<<<dim3(CB, SZ_B / BM), 256>>>();
    combine_kernel<<<SZ_B, 256>>>(xs);
    mean_kernel<<<1, SZ_B>>>(out);
}

// round 11
// speedup vs baseline: 6.2140x; 1.1353x over previous
#include <cuda_runtime.h>
#include <cuda_bf16.h>
#include <cstdint>
#include <math.h>

#define NB_C   100000
#define SZ_D   64
#define SZ_B   1024
#define BM     128
#define BN     128
#define CB     ((NB_C + BN - 1) / BN)   // 782 class blocks
#define N_PAD  (CB * BN - NB_C)         // 96 pad classes, each contributes exactly 1.0
#define GRIDX  38                       // 38 x 8 = 304 CTAs = 2 per SM (152 SMs)
#define LOG2E  1.4426950408889634f

// ---- device scratch (no allocations allowed) ----
__device__ float          g_Pn [(size_t)NB_C * SZ_D];  // normalized proxies fp32 (combine only)
__device__ __nv_bfloat16  g_Pb [(size_t)NB_C * SZ_D];  // normalized proxies bf16 (GEMM B)
__device__ __nv_bfloat16  g_Xb [(size_t)SZ_B * SZ_D];  // xs bf16 (GEMM A)
__device__ float          g_psq[NB_C];                 // sum(Pn^2), exact fp32
__device__ float          g_partial[(size_t)SZ_B * CB];
__device__ float          g_persample[SZ_B];
__device__ int            g_ys[SZ_B];

// ---------------- PTX helpers ----------------
__device__ __forceinline__ void ldsm_x4(unsigned& r0, unsigned& r1, unsigned& r2, unsigned& r3,
                                        unsigned saddr) {
    asm volatile("ldmatrix.sync.aligned.m8n8.x4.shared.b16 {%0,%1,%2,%3}, [%4];"
                 : "=r"(r0), "=r"(r1), "=r"(r2), "=r"(r3) : "r"(saddr));
}
__device__ __forceinline__ void mma_bf16(float* d, const unsigned* a, const unsigned* b) {
    asm("mma.sync.aligned.m16n8k16.row.col.f32.bf16.bf16.f32 "
        "{%0,%1,%2,%3}, {%4,%5,%6,%7}, {%8,%9}, {%0,%1,%2,%3};"
        : "+f"(d[0]), "+f"(d[1]), "+f"(d[2]), "+f"(d[3])
        : "r"(a[0]), "r"(a[1]), "r"(a[2]), "r"(a[3]), "r"(b[0]), "r"(b[1]));
}
__device__ __forceinline__ void cp_async16(unsigned dst, const void* src, unsigned sz) {
    asm volatile("cp.async.cg.shared.global [%0], [%1], 16, %2;"
                 :: "r"(dst), "l"(src), "r"(sz) : "memory");
}
__device__ __forceinline__ void cp_commit() { asm volatile("cp.async.commit_group;" ::: "memory"); }
template<int N> __device__ __forceinline__ void cp_wait() {
    asm volatile("cp.async.wait_group %0;" :: "n"(N) : "memory");
}
__device__ __forceinline__ float ex2(float x) {
    float y; asm("ex2.approx.ftz.f32 %0, %1;" : "=f"(y) : "f"(x)); return y;
}

// ============ Kernel 0: decode labels (int32 vs int64 robust) ============
__global__ void decode_ys_kernel(const int* __restrict__ ys32) {
    __shared__ int nonzero_odd;
    const int tid = threadIdx.x;           // 1024 threads
    if (tid == 0) nonzero_odd = 0;
    __syncthreads();
    if (tid < SZ_B / 2) {
        if (ys32[2 * tid + 1] != 0) atomicOr(&nonzero_odd, 1);
    }
    __syncthreads();
    if (nonzero_odd) g_ys[tid] = ys32[tid];
    else             g_ys[tid] = (int)((const long long*)ys32)[tid];
}

// ============ Kernel 0b: xs -> bf16 ============
__global__ void cvt_xs_kernel(const float* __restrict__ xs) {
    int i = blockIdx.x * 256 + threadIdx.x;          // 16384 float4 groups
    float4 v = *(const float4*)(xs + (size_t)i * 4);
    __nv_bfloat162 lo = __floats2bfloat162_rn(v.x, v.y);
    __nv_bfloat162 hi = __floats2bfloat162_rn(v.z, v.w);
    *(unsigned*)(g_Xb + (size_t)i * 4)     = *(unsigned*)&lo;
    *(unsigned*)(g_Xb + (size_t)i * 4 + 2) = *(unsigned*)&hi;
}

// ================= Kernel A: row-normalize proxies (fp32 + bf16 out) =================
__global__ void normalize_kernel(const float* __restrict__ proxies) {
    int row  = blockIdx.x * 8 + (threadIdx.x >> 5);
    int lane = threadIdx.x & 31;
    if (row >= NB_C) return;
    const float2 v = *(const float2*)(proxies + (size_t)row * SZ_D + lane * 2);
    float s = v.x * v.x + v.y * v.y;
    #pragma unroll
    for (int o = 16; o; o >>= 1) s += __shfl_xor_sync(0xffffffffu, s, o);
    float norm = sqrtf(s);
    float inv  = 1.0f / fmaxf(norm, 1e-12f);
    float2 w; w.x = v.x * inv; w.y = v.y * inv;
    *(float2*)(g_Pn + (size_t)row * SZ_D + lane * 2) = w;
    __nv_bfloat162 wb = __floats2bfloat162_rn(w.x, w.y);
    *(unsigned*)(g_Pb + (size_t)row * SZ_D + lane * 2) = *(unsigned*)&wb;
    if (lane == 0) g_psq[row] = s * inv * inv;
}

// ===== Kernel B: persistent bf16 mma GEMM, cp.async double-buffered B =====
// 4 warps, warp tile 32x128 (whole rows per warp -> no cross-warp combine).
// A tile loaded ONCE per CTA; B tiles stream through 2 smem buffers.
// XOR-swizzled 128B-stride tiles (conflict-free ldmatrix, no padding).
// Unmasked exp-sum (pads = exactly +1.0 each, positive term fixed in combine).
__global__ void __launch_bounds__(128, 2)
gemm_lse_kernel(void) {
    __shared__ __align__(1024) __nv_bfloat16 As[BM * 64];        // 16 KB
    __shared__ __align__(1024) __nv_bfloat16 Bs[2][BN * 64];     // 32 KB

    const int tid  = threadIdx.x;          // 128
    const int lane = tid & 31;
    const int wid  = tid >> 5;
    const int qr   = lane >> 2;            // 0..7
    const int qc   = lane & 3;             // 0..3
    const int row0 = blockIdx.y * BM;

    const unsigned As_a = (unsigned)__cvta_generic_to_shared(As);
    const unsigned Bs_a = (unsigned)__cvta_generic_to_shared(Bs);
    const int      rx   = tid & 7;

    // -- A fill (once): thread tid owns row tid, 8 swizzled 16B chunks --
    {
        const __nv_bfloat16* src = g_Xb + (size_t)(row0 + tid) * SZ_D;
        unsigned dst = As_a + tid * 128;
        #pragma unroll
        for (int c = 0; c < 8; c++)
            cp_async16(dst + ((c ^ rx) << 4), src + c * 8, 16u);
    }
    // -- first B prefetch into buffer 0 --
    {
        int cls = blockIdx.x * BN + tid;
        const __nv_bfloat16* src = g_Pb + (size_t)cls * SZ_D;
        unsigned dst = Bs_a + tid * 128;
        unsigned sz = (cls < NB_C) ? 16u : 0u;
        #pragma unroll
        for (int c = 0; c < 8; c++)
            cp_async16(dst + ((c ^ rx) << 4), src + c * 8, sz);
    }
    cp_commit();

    // ldmatrix lane address components (match validated R9 mapping, + swizzle)
    const unsigned rA0   = wid * 32 + (lane & 15);        // mf=0 row
    const unsigned rA1   = rA0 + 16;                      // mf=1 row
    const unsigned cAoff = (lane >> 4);                   // chunk lo bit
    const unsigned rBl   = ((lane >> 4) << 3) + (lane & 7);
    const unsigned cBoff = ((lane >> 3) & 1);

    int buf = 0;
    for (int cb = blockIdx.x; cb < CB; cb += GRIDX) {
        const int next = cb + GRIDX;
        if (next < CB) {
            int cls = next * BN + tid;
            const __nv_bfloat16* src = g_Pb + (size_t)cls * SZ_D;
            unsigned dst = Bs_a + (buf ^ 1) * (BN * 128) + tid * 128;
            unsigned sz = (cls < NB_C) ? 16u : 0u;
            #pragma unroll
            for (int c = 0; c < 8; c++)
                cp_async16(dst + ((c ^ rx) << 4), src + c * 8, sz);
            cp_commit();
            cp_wait<1>();
        } else {
            cp_wait<0>();
        }
        __syncthreads();

        const unsigned Bb = Bs_a + buf * (BN * 128);
        float acc[2][16][4];
        #pragma unroll
        for (int mf = 0; mf < 2; mf++)
            #pragma unroll
            for (int nf = 0; nf < 16; nf++)
                #pragma unroll
                for (int c = 0; c < 4; c++) acc[mf][nf][c] = 0.0f;

        #pragma unroll
        for (int s = 0; s < 4; s++) {                    // 4 k16-steps
            unsigned a[2][4], b[16][2];
            unsigned cA = s * 2 + cAoff;
            ldsm_x4(a[0][0], a[0][1], a[0][2], a[0][3],
                    As_a + rA0 * 128 + (((cA ^ (rA0 & 7)) & 7) << 4));
            ldsm_x4(a[1][0], a[1][1], a[1][2], a[1][3],
                    As_a + rA1 * 128 + (((cA ^ (rA1 & 7)) & 7) << 4));
            #pragma unroll
            for (int g = 0; g < 8; g++) {
                unsigned r = g * 16 + rBl;
                unsigned cB = s * 2 + cBoff;
                ldsm_x4(b[2 * g][0], b[2 * g][1], b[2 * g + 1][0], b[2 * g + 1][1],
                        Bb + r * 128 + (((cB ^ (r & 7)) & 7) << 4));
            }
            #pragma unroll
            for (int mf = 0; mf < 2; mf++)
                #pragma unroll
                for (int nf = 0; nf < 16; nf++)
                    mma_bf16(acc[mf][nf], a[mf], b[nf]);
        }

        // -- epilogue: e = exp2(2*log2e*acc - psq*log2e), no masks --
        float q2[16][2];
        #pragma unroll
        for (int nf = 0; nf < 16; nf++) {
            int cls0 = cb * BN + nf * 8 + qc * 2;        // even; NB_C even -> pair all-or-none
            float2 q = (cls0 < NB_C) ? *(const float2*)(g_psq + cls0)
                                     : make_float2(0.0f, 0.0f);
            q2[nf][0] = q.x * LOG2E;
            q2[nf][1] = q.y * LOG2E;
        }
        const float TWO_L2E = 2.0f * LOG2E;
        #pragma unroll
        for (int mf = 0; mf < 2; mf++) {
            float s0 = 0.0f, s1 = 0.0f;
            #pragma unroll
            for (int nf = 0; nf < 16; nf++) {
                s0 += ex2(fmaf(TWO_L2E, acc[mf][nf][0], -q2[nf][0]));
                s0 += ex2(fmaf(TWO_L2E, acc[mf][nf][1], -q2[nf][1]));
                s1 += ex2(fmaf(TWO_L2E, acc[mf][nf][2], -q2[nf][0]));
                s1 += ex2(fmaf(TWO_L2E, acc[mf][nf][3], -q2[nf][1]));
            }
            #pragma unroll
            for (int o = 1; o <= 2; o <<= 1) {
                s0 += __shfl_xor_sync(0xffffffffu, s0, o);
                s1 += __shfl_xor_sync(0xffffffffu, s1, o);
            }
            if (qc == 0) {
                int r = row0 + wid * 32 + mf * 16 + qr;
                g_partial[(size_t)r * CB + cb]       = s0;
                g_partial[(size_t)(r + 8) * CB + cb] = s1;
            }
        }
        __syncthreads();        // everyone done with buf before it is refilled
        buf ^= 1;
    }
}

// ===== Kernel C: combine partials, subtract pads + positive term (exact fp32) =====
__global__ void combine_kernel(const float* __restrict__ xs) {
    const int row = blockIdx.x;
    const int tid = threadIdx.x;   // 256 threads
    const int y   = g_ys[row];

    float S = 0.0f;
    for (int p = tid; p < CB; p += 256) S += g_partial[(size_t)row * CB + p];

    float d = 0.0f;
    if (tid < SZ_D) d = xs[(size_t)row * SZ_D + tid] * g_Pn[(size_t)y * SZ_D + tid];

    #pragma unroll
    for (int o = 16; o; o >>= 1) {
        S += __shfl_xor_sync(0xffffffffu, S, o);
        d += __shfl_xor_sync(0xffffffffu, d, o);
    }
    __shared__ float sS[8], sD[8];
    int w = tid >> 5, lane = tid & 31;
    if (lane == 0) { sS[w] = S; sD[w] = d; }
    __syncthreads();
    if (tid == 0) {
        float St = 0.0f, Dt = 0.0f;
        #pragma unroll
        for (int k = 0; k < 8; k++) { St += sS[k]; Dt += sD[k]; }
        float psq_y = g_psq[y];
        // remove the 96 pad ones (exact) and the positive-class exp term
        float Sneg = St - (float)N_PAD - __expf(fmaf(2.0f, Dt, -psq_y));
        // per_sample = d_pos + log_n ; the ||x||^2 terms cancel exactly
        g_persample[row] = psq_y - 2.0f * Dt + logf(Sneg);
    }
}

// ===== Kernel D: mean over batch =====
__global__ void mean_kernel(float* __restrict__ out) {
    const int tid = threadIdx.x;   // 1024
    float v = g_persample[tid];
    #pragma unroll
    for (int o = 16; o; o >>= 1) v += __shfl_xor_sync(0xffffffffu, v, o);
    __shared__ float s[32];
    int w = tid >> 5, lane = tid & 31;
    if (lane == 0) s[w] = v;
    __syncthreads();
    if (tid < 32) {
        float t = s[tid];
        #pragma unroll
        for (int o = 16; o; o >>= 1) t += __shfl_xor_sync(0xffffffffu, t, o);
        if (tid == 0) out[0] = t * (1.0f / (float)SZ_B);
    }
}

extern "C" void kernel_launch(void* const* d_in, const int* in_sizes, int n_in,
                              void* d_out, int out_size) {
    const float* xs      = (const float*)d_in[0];
    const int*   ys_raw  = (const int*)d_in[1];
    const float* proxies = (const float*)d_in[2];
    float*       out     = (float*)d_out;

    decode_ys_kernel<<<1, SZ_B>>>(ys_raw);
    cvt_xs_kernel<<<(SZ_B * SZ_D / 4) / 256, 256>>>(xs);
    normalize_kernel<<<(NB_C + 7) / 8, 256>>>(proxies);
    gemm_lse_kernel<<<dim3(GRIDX, SZ_B / BM), 128>>>();
    combine_kernel<<<SZ_B, 256>>>(xs);
    mean_kernel<<<1, SZ_B>>>(out);
}

// round 13
// speedup vs baseline: 7.3183x; 1.1777x over previous
#include <cuda_runtime.h>
#include <cuda_bf16.h>
#include <cstdint>
#include <math.h>

#define NB_C   100000
#define SZ_D   64
#define SZ_B   1024
#define BM     128
#define BN     128
#define CB     ((NB_C + BN - 1) / BN)   // 782 class blocks
#define N_PAD  (CB * BN - NB_C)         // 96 pad classes, each contributes exactly 1.0
#define GRIDX  38                       // 38 x 8 = 304 CTAs = 2 per SM (152 SMs)
#define LOG2E  1.4426950408889634f

// ---- device scratch (no allocations allowed) ----
__device__ float          g_Pn [(size_t)NB_C * SZ_D];  // normalized proxies fp32 (combine only)
__device__ __nv_bfloat16  g_Pb [(size_t)NB_C * SZ_D];  // normalized proxies bf16 (GEMM B)
__device__ __nv_bfloat16  g_Xb [(size_t)SZ_B * SZ_D];  // xs bf16 (GEMM A)
__device__ float          g_psq[NB_C];                 // sum(Pn^2), exact fp32
__device__ float          g_partial[(size_t)SZ_B * CB];
__device__ float          g_persample[SZ_B];
__device__ int            g_ys[SZ_B];

// ---------------- PTX helpers ----------------
__device__ __forceinline__ void ldsm_x4(unsigned& r0, unsigned& r1, unsigned& r2, unsigned& r3,
                                        unsigned saddr) {
    asm volatile("ldmatrix.sync.aligned.m8n8.x4.shared.b16 {%0,%1,%2,%3}, [%4];"
                 : "=r"(r0), "=r"(r1), "=r"(r2), "=r"(r3) : "r"(saddr));
}
__device__ __forceinline__ void mma_bf16(float* d, const unsigned* a, const unsigned* b) {
    asm("mma.sync.aligned.m16n8k16.row.col.f32.bf16.bf16.f32 "
        "{%0,%1,%2,%3}, {%4,%5,%6,%7}, {%8,%9}, {%0,%1,%2,%3};"
        : "+f"(d[0]), "+f"(d[1]), "+f"(d[2]), "+f"(d[3])
        : "r"(a[0]), "r"(a[1]), "r"(a[2]), "r"(a[3]), "r"(b[0]), "r"(b[1]));
}
__device__ __forceinline__ void cp_async16(unsigned dst, const void* src, unsigned sz) {
    asm volatile("cp.async.cg.shared.global [%0], [%1], 16, %2;"
                 :: "r"(dst), "l"(src), "r"(sz) : "memory");
}
__device__ __forceinline__ void cp_commit() { asm volatile("cp.async.commit_group;" ::: "memory"); }
template<int N> __device__ __forceinline__ void cp_wait() {
    asm volatile("cp.async.wait_group %0;" :: "n"(N) : "memory");
}
__device__ __forceinline__ float ex2(float x) {
    float y; asm("ex2.approx.ftz.f32 %0, %1;" : "=f"(y) : "f"(x)); return y;
}

// ============ Kernel 0: decode labels (int32 vs int64 robust) ============
__global__ void decode_ys_kernel(const int* __restrict__ ys32) {
    __shared__ int nonzero_odd;
    const int tid = threadIdx.x;           // 1024 threads
    if (tid == 0) nonzero_odd = 0;
    __syncthreads();
    if (tid < SZ_B / 2) {
        if (ys32[2 * tid + 1] != 0) atomicOr(&nonzero_odd, 1);
    }
    __syncthreads();
    if (nonzero_odd) g_ys[tid] = ys32[tid];
    else             g_ys[tid] = (int)((const long long*)ys32)[tid];
}

// ============ Kernel 0b: xs -> bf16 ============
__global__ void cvt_xs_kernel(const float* __restrict__ xs) {
    int i = blockIdx.x * 256 + threadIdx.x;          // 16384 float4 groups
    float4 v = *(const float4*)(xs + (size_t)i * 4);
    __nv_bfloat162 lo = __floats2bfloat162_rn(v.x, v.y);
    __nv_bfloat162 hi = __floats2bfloat162_rn(v.z, v.w);
    *(unsigned*)(g_Xb + (size_t)i * 4)     = *(unsigned*)&lo;
    *(unsigned*)(g_Xb + (size_t)i * 4 + 2) = *(unsigned*)&hi;
}

// ================= Kernel A: row-normalize proxies (fp32 + bf16 out) =================
__global__ void normalize_kernel(const float* __restrict__ proxies) {
    int row  = blockIdx.x * 8 + (threadIdx.x >> 5);
    int lane = threadIdx.x & 31;
    if (row >= NB_C) return;
    const float2 v = *(const float2*)(proxies + (size_t)row * SZ_D + lane * 2);
    float s = v.x * v.x + v.y * v.y;
    #pragma unroll
    for (int o = 16; o; o >>= 1) s += __shfl_xor_sync(0xffffffffu, s, o);
    float norm = sqrtf(s);
    float inv  = 1.0f / fmaxf(norm, 1e-12f);
    float2 w; w.x = v.x * inv; w.y = v.y * inv;
    *(float2*)(g_Pn + (size_t)row * SZ_D + lane * 2) = w;
    __nv_bfloat162 wb = __floats2bfloat162_rn(w.x, w.y);
    *(unsigned*)(g_Pb + (size_t)row * SZ_D + lane * 2) = *(unsigned*)&wb;
    if (lane == 0) g_psq[row] = s * inv * inv;
}

// ===== Kernel B: persistent bf16 mma GEMM, 8 warps, cp.async double-buffered B =====
// Warp tile 16x128 (whole rows per warp -> no cross-warp combine); acc = 64 regs ->
// 2 CTAs/SM at 256 threads (16 warps/SM). A loaded once; B streams via 2 buffers.
__global__ void __launch_bounds__(256, 2)
gemm_lse_kernel(void) {
    __shared__ __align__(1024) __nv_bfloat16 As[BM * 64];        // 16 KB
    __shared__ __align__(1024) __nv_bfloat16 Bs[2][BN * 64];     // 32 KB

    const int tid  = threadIdx.x;          // 256
    const int lane = tid & 31;
    const int wid  = tid >> 5;             // 0..7
    const int qr   = lane >> 2;            // 0..7
    const int qc   = lane & 3;             // 0..3
    const int row0 = blockIdx.y * BM;
    const int mb   = wid * 16;             // warp's 16 rows

    const unsigned As_a = (unsigned)__cvta_generic_to_shared(As);
    const unsigned Bs_a = (unsigned)__cvta_generic_to_shared(Bs);

    // -- A fill (once): 1024 16B chunks over 256 threads --
    #pragma unroll
    for (int i = 0; i < 4; i++) {
        int idx = tid + i * 256;
        int r = idx >> 3, c = idx & 7;
        cp_async16(As_a + r * 128 + ((c ^ (r & 7)) << 4),
                   g_Xb + (size_t)(row0 + r) * SZ_D + c * 8, 16u);
    }
    // -- first B prefetch into buffer 0 --
    #pragma unroll
    for (int i = 0; i < 4; i++) {
        int idx = tid + i * 256;
        int r = idx >> 3, c = idx & 7;
        int cls = blockIdx.x * BN + r;
        cp_async16(Bs_a + r * 128 + ((c ^ (r & 7)) << 4),
                   g_Pb + (size_t)cls * SZ_D + c * 8, (cls < NB_C) ? 16u : 0u);
    }
    cp_commit();

    // ldmatrix lane address components
    const unsigned rA    = mb + (lane & 15);
    const unsigned cAoff = (lane >> 4);
    const unsigned rBl   = ((lane >> 4) << 3) + (lane & 7);
    const unsigned cBoff = ((lane >> 3) & 1);

    int buf = 0;
    for (int cb = blockIdx.x; cb < CB; cb += GRIDX) {
        const int next = cb + GRIDX;
        if (next < CB) {
            #pragma unroll
            for (int i = 0; i < 4; i++) {
                int idx = tid + i * 256;
                int r = idx >> 3, c = idx & 7;
                int cls = next * BN + r;
                cp_async16(Bs_a + (buf ^ 1) * (BN * 128) + r * 128 + ((c ^ (r & 7)) << 4),
                           g_Pb + (size_t)cls * SZ_D + c * 8, (cls < NB_C) ? 16u : 0u);
            }
            cp_commit();
            cp_wait<1>();
        } else {
            cp_wait<0>();
        }
        __syncthreads();

        const unsigned Bb = Bs_a + buf * (BN * 128);
        float acc[16][4];
        #pragma unroll
        for (int nf = 0; nf < 16; nf++)
            #pragma unroll
            for (int c = 0; c < 4; c++) acc[nf][c] = 0.0f;

        #pragma unroll
        for (int s = 0; s < 4; s++) {                    // 4 k16-steps
            unsigned a[4], b[16][2];
            unsigned cA = s * 2 + cAoff;
            ldsm_x4(a[0], a[1], a[2], a[3],
                    As_a + rA * 128 + (((cA ^ (rA & 7)) & 7) << 4));
            #pragma unroll
            for (int g = 0; g < 8; g++) {
                unsigned r = g * 16 + rBl;
                unsigned cB = s * 2 + cBoff;
                ldsm_x4(b[2 * g][0], b[2 * g][1], b[2 * g + 1][0], b[2 * g + 1][1],
                        Bb + r * 128 + (((cB ^ (r & 7)) & 7) << 4));
            }
            #pragma unroll
            for (int nf = 0; nf < 16; nf++)
                mma_bf16(acc[nf], a, b[nf]);
        }

        // -- epilogue: e = exp2(2*log2e*acc - psq*log2e), no masks --
        const float TWO_L2E = 2.0f * LOG2E;
        float s0 = 0.0f, s1 = 0.0f;
        #pragma unroll
        for (int nf = 0; nf < 16; nf++) {
            int cls0 = cb * BN + nf * 8 + qc * 2;        // even; NB_C even -> pair all-or-none
            float2 q = (cls0 < NB_C) ? *(const float2*)(g_psq + cls0)
                                     : make_float2(0.0f, 0.0f);
            float q0 = q.x * LOG2E, q1 = q.y * LOG2E;
            s0 += ex2(fmaf(TWO_L2E, acc[nf][0], -q0));
            s0 += ex2(fmaf(TWO_L2E, acc[nf][1], -q1));
            s1 += ex2(fmaf(TWO_L2E, acc[nf][2], -q0));
            s1 += ex2(fmaf(TWO_L2E, acc[nf][3], -q1));
        }
        #pragma unroll
        for (int o = 1; o <= 2; o <<= 1) {
            s0 += __shfl_xor_sync(0xffffffffu, s0, o);
            s1 += __shfl_xor_sync(0xffffffffu, s1, o);
        }
        if (qc == 0) {
            int r = row0 + mb + qr;
            g_partial[(size_t)r * CB + cb]       = s0;
            g_partial[(size_t)(r + 8) * CB + cb] = s1;
        }
        __syncthreads();        // everyone done with buf before it is refilled
        buf ^= 1;
    }
}

// ===== Kernel C: combine partials, subtract pads + positive term (exact fp32) =====
__global__ void combine_kernel(const float* __restrict__ xs) {
    const int row = blockIdx.x;
    const int tid = threadIdx.x;   // 256 threads
    const int y   = g_ys[row];

    float S = 0.0f;
    for (int p = tid; p < CB; p += 256) S += g_partial[(size_t)row * CB + p];

    float d = 0.0f;
    if (tid < SZ_D) d = xs[(size_t)row * SZ_D + tid] * g_Pn[(size_t)y * SZ_D + tid];

    #pragma unroll
    for (int o = 16; o; o >>= 1) {
        S += __shfl_xor_sync(0xffffffffu, S, o);
        d += __shfl_xor_sync(0xffffffffu, d, o);
    }
    __shared__ float sS[8], sD[8];
    int w = tid >> 5, lane = tid & 31;
    if (lane == 0) { sS[w] = S; sD[w] = d; }
    __syncthreads();
    if (tid == 0) {
        float St = 0.0f, Dt = 0.0f;
        #pragma unroll
        for (int k = 0; k < 8; k++) { St += sS[k]; Dt += sD[k]; }
        float psq_y = g_psq[y];
        // remove the 96 pad ones (exact) and the positive-class exp term
        float Sneg = St - (float)N_PAD - __expf(fmaf(2.0f, Dt, -psq_y));
        // per_sample = d_pos + log_n ; the ||x||^2 terms cancel exactly
        g_persample[row] = psq_y - 2.0f * Dt + logf(Sneg);
    }
}

// ===== Kernel D: mean over batch =====
__global__ void mean_kernel(float* __restrict__ out) {
    const int tid = threadIdx.x;   // 1024
    float v = g_persample[tid];
    #pragma unroll
    for (int o = 16; o; o >>= 1) v += __shfl_xor_sync(0xffffffffu, v, o);
    __shared__ float s[32];
    int w = tid >> 5, lane = tid & 31;
    if (lane == 0) s[w] = v;
    __syncthreads();
    if (tid < 32) {
        float t = s[tid];
        #pragma unroll
        for (int o = 16; o; o >>= 1) t += __shfl_xor_sync(0xffffffffu, t, o);
        if (tid == 0) out[0] = t * (1.0f / (float)SZ_B);
    }
}

extern "C" void kernel_launch(void* const* d_in, const int* in_sizes, int n_in,
                              void* d_out, int out_size) {
    const float* xs      = (const float*)d_in[0];
    const int*   ys_raw  = (const int*)d_in[1];
    const float* proxies = (const float*)d_in[2];
    float*       out     = (float*)d_out;

    decode_ys_kernel<<<1, SZ_B>>>(ys_raw);
    cvt_xs_kernel<<<(SZ_B * SZ_D / 4) / 256, 256>>>(xs);
    normalize_kernel<<<(NB_C + 7) / 8, 256>>>(proxies);
    gemm_lse_kernel<<<dim3(GRIDX, SZ_B / BM), 256>>>();
    combine_kernel<<<SZ_B, 256>>>(xs);
    mean_kernel<<<1, SZ_B>>>(out);
}